// round 3
// baseline (speedup 1.0000x reference)
#include <cuda_runtime.h>

// TransientCombNoise: B=32, T=2000, BLOCK=64, SR=16000, MAX_DELAY=480
// N = B*T = 64000 independent rows of 64 samples.
//
// Key simplification (valid for these input ranges):
//   delay = int(32 + 32*bandwidth), bandwidth = 0.05 + p3*0.95 in [0.05, 1)
//   => delay in [33, 63].  For s < delay the comb reads never-written (zero)
//   buffer cells; for s >= delay it reads y[s-delay], and s-delay <= 30 < delay
//   so that value itself had no feedback. Hence:
//       y[s] = x[s] + (s >= delay ? tilt * x[s-delay] : 0)
//   where x = noise * exp(-s/attack) * energy.
// Then out = y / sqrt(mean(y^2) + 1e-5).

#define N_ROWS (32 * 2000)

__global__ void __launch_bounds__(256)
transient_comb_kernel(const float* __restrict__ params,  // [N,4]
                      const float* __restrict__ noise,   // [N,64]
                      float* __restrict__ out)           // [N,64]
{
    const int warp = (blockIdx.x * blockDim.x + threadIdx.x) >> 5;
    const int lane = threadIdx.x & 31;
    if (warp >= N_ROWS) return;

    // Broadcast load of this row's 4 params (same address across warp -> 1 req)
    const float4 p = *reinterpret_cast<const float4*>(params + 4u * (unsigned)warp);

    const float attack_s       = 0.0005f + p.x * 0.0495f;
    const float energy         = p.y;
    const float tilt           = p.z * 2.0f - 1.0f;
    // Replicate XLA's separate-op fp32 rounding for the int-truncation path:
    const float bandwidth      = __fadd_rn(0.05f, __fmul_rn(p.w, 0.95f));
    const float dval           = __fmul_rn(64.0f,
                                   __fadd_rn(0.5f, __fmul_rn(0.5f, bandwidth)));
    int delay = (int)dval;                       // truncation == astype(int32)
    delay = min(max(delay, 1), 480);

    const float attack_samples = fmaxf(attack_s * 16000.0f, 1.0f);

    // Two samples per lane: s0 = lane (0..31), s1 = lane+32 (32..63)
    const float* nrow = noise + 64u * (unsigned)warp;
    const float x0 = nrow[lane];
    const float x1 = nrow[lane + 32];

    const float e0 = expf(-((float)lane)        / attack_samples);
    const float e1 = expf(-((float)(lane + 32)) / attack_samples);

    const float b0 = x0 * e0 * energy;
    const float b1 = x1 * e1 * energy;

    // Comb tap. delay in [33,63]:
    //   s0 = lane <= 31 < delay  -> no tap for low half
    //   s1 = lane+32: tap index idx = s1 - delay in [-31, 30]; when idx >= 0
    //   the source sample is the LOW sample of lane idx (idx < 32 guaranteed).
    const float y0  = b0;
    const int   idx = lane + 32 - delay;
    const float src = __shfl_sync(0xffffffffu, b0, idx & 31);
    const float y1  = b1 + ((idx >= 0) ? tilt * src : 0.0f);

    // RMS over the 64 samples of this row (warp-wide reduce)
    float ss = y0 * y0 + y1 * y1;
    #pragma unroll
    for (int o = 16; o > 0; o >>= 1)
        ss += __shfl_xor_sync(0xffffffffu, ss, o);

    const float rms = sqrtf(ss * (1.0f / 64.0f) + 1e-5f);
    const float inv = 1.0f / rms;

    float* orow = out + 64u * (unsigned)warp;
    orow[lane]      = y0 * inv;
    orow[lane + 32] = y1 * inv;
}

extern "C" void kernel_launch(void* const* d_in, const int* in_sizes, int n_in,
                              void* d_out, int out_size)
{
    const float* params = (const float*)d_in[0];  // [32,2000,4]
    const float* noise  = (const float*)d_in[1];  // [32,2000,64]
    float* out          = (float*)d_out;          // [32, 2000*64]

    (void)in_sizes; (void)n_in; (void)out_size;

    // One warp per row: 64000 warps -> 8000 blocks of 256 threads (8 warps)
    const int threads = 256;
    const int blocks  = (N_ROWS * 32 + threads - 1) / threads;
    transient_comb_kernel<<<blocks, threads>>>(params, noise, out);
}

// round 5
// speedup vs baseline: 1.2079x; 1.2079x over previous
#include <cuda_runtime.h>

// TransientCombNoise: B=32, T=2000, BLOCK=64, SR=16000, MAX_DELAY=480
// N = B*T = 64000 independent rows of 64 samples.
//
// Simplifications (valid for these input ranges):
//   delay = int(32 + 32*bandwidth) in [33, 63]  =>  single FIR tap:
//       y[s] = x[s] + (s >= delay ? tilt * x[s-delay] : 0)
//   envelope exp(-s/a) = r^s, r = exp(-1/a)  =>  ONE expf per row,
//   powers via binary decomposition (MUFU pressure 64x lower).
// Then out = y * rsqrt(mean(y^2) + 1e-5).

#define N_ROWS (32 * 2000)

__global__ void __launch_bounds__(256)
transient_comb_kernel(const float* __restrict__ params,  // [N,4]
                      const float* __restrict__ noise,   // [N,64]
                      float* __restrict__ out)           // [N,64]
{
    const int lane    = threadIdx.x & 31;
    const int gwarp   = (blockIdx.x * blockDim.x + threadIdx.x) >> 5;
    const int nwarps  = (gridDim.x * blockDim.x) >> 5;

    for (int row = gwarp; row < N_ROWS; row += nwarps) {
        // Broadcast load of this row's 4 params (uniform address -> 1 req)
        const float4 p = *reinterpret_cast<const float4*>(params + 4u * (unsigned)row);

        const float energy = p.y;
        const float tilt   = p.z * 2.0f - 1.0f;

        // Replicate XLA's separate-op fp32 rounding at the int-trunc boundary:
        const float bandwidth = __fadd_rn(0.05f, __fmul_rn(p.w, 0.95f));
        const float dval      = __fmul_rn(64.0f,
                                  __fadd_rn(0.5f, __fmul_rn(0.5f, bandwidth)));
        int delay = (int)dval;
        delay = min(max(delay, 1), 480);

        const float attack_samples =
            fmaxf((0.0005f + p.x * 0.0495f) * 16000.0f, 1.0f);   // in [8, 792]

        // Envelope as geometric sequence: e[s] = r^s, one MUFU per row.
        const float r   = __expf(-1.0f / attack_samples);        // in (0.88, 0.999)
        const float r2  = r  * r;
        const float r4  = r2 * r2;
        const float r8  = r4 * r4;
        const float r16 = r8 * r8;
        const float r32 = r16 * r16;

        float e = (lane & 1)  ? r   : 1.0f;
        e      *= (lane & 2)  ? r2  : 1.0f;
        e      *= (lane & 4)  ? r4  : 1.0f;
        e      *= (lane & 8)  ? r8  : 1.0f;
        e      *= (lane & 16) ? r16 : 1.0f;                      // e = r^lane

        const float ee0 = e * energy;                            // env*energy, s=lane
        const float ee1 = ee0 * r32;                             // s=lane+32

        // Two samples per lane: s0 = lane, s1 = lane+32 (coalesced)
        const float* nrow = noise + 64u * (unsigned)row;
        const float x0 = nrow[lane];
        const float x1 = nrow[lane + 32];

        const float b0 = x0 * ee0;
        const float b1 = x1 * ee1;

        // Comb tap: delay in [33,63] => only high half taps, source is the
        // LOW sample of lane (lane+32-delay), which is in [-31, 30].
        const int   idx = lane + 32 - delay;
        const float src = __shfl_sync(0xffffffffu, b0, idx & 31);
        const float y0  = b0;
        const float y1  = b1 + ((idx >= 0) ? tilt * src : 0.0f);

        // RMS over the row (warp butterfly reduce)
        float ss = y0 * y0 + y1 * y1;
        #pragma unroll
        for (int o = 16; o > 0; o >>= 1)
            ss += __shfl_xor_sync(0xffffffffu, ss, o);

        const float inv = rsqrtf(fmaf(ss, (1.0f / 64.0f), 1e-5f));

        float* orow = out + 64u * (unsigned)row;
        orow[lane]      = y0 * inv;
        orow[lane + 32] = y1 * inv;
    }
}

extern "C" void kernel_launch(void* const* d_in, const int* in_sizes, int n_in,
                              void* d_out, int out_size)
{
    const float* params = (const float*)d_in[0];  // [32,2000,4]
    const float* noise  = (const float*)d_in[1];  // [32,2000,64]
    float* out          = (float*)d_out;          // [32, 2000*64]

    (void)in_sizes; (void)n_in; (void)out_size;

    // Persistent grid: fill the chip exactly once (148 SMs x 8 blocks x 256 thr
    // = 64 warps/SM), grid-stride over the 64000 rows. Avoids ~7 launch waves.
    const int threads = 256;
    const int blocks  = 1184;
    transient_comb_kernel<<<blocks, threads>>>(params, noise, out);
}

// round 9
// speedup vs baseline: 1.4878x; 1.2317x over previous
#include <cuda_runtime.h>

// TransientCombNoise: B=32, T=2000, BLOCK=64, SR=16000, MAX_DELAY=480
// N = 64000 independent rows of 64 samples.
//
//   delay = int(32 + 32*bandwidth) in [33, 63]  =>  single FIR tap:
//       y[s] = x[s] + (s >= delay ? tilt * x[s-delay] : 0)
//   envelope exp(-s/a) = r^s via binary decomposition (1 expf per ROW).
//   out = y * rsqrt(mean(y^2) + 1e-5)
//
// Issue-bound kernel => minimize warp-instructions per row:
//   - params for 8 rows computed once per warp (lane l -> row base+(l&7)),
//     broadcast per row via shfl.
//   - decomposition predicates (lane&k) hoisted out of the loop.
//   - warp RMS reduce via 5-step shfl_xor butterfly (redux.f32 is NOT
//     available on sm_103 -- ptxas rejects it).
//   - fully unrolled 8-row loop: all gmem offsets are immediates.

#define N_ROWS (32 * 2000)
#define BATCH  8
#define NWARPS (N_ROWS / BATCH)   // 8000

__global__ void __launch_bounds__(256)
transient_comb_kernel(const float4* __restrict__ params4, // [N] float4
                      const float*  __restrict__ noise,   // [N,64]
                      float*        __restrict__ out)     // [N,64]
{
    const int warp = (blockIdx.x * blockDim.x + threadIdx.x) >> 5;
    const int lane = threadIdx.x & 31;
    if (warp >= NWARPS) return;

    const int base = warp * BATCH;

    // ---- prologue: per-lane params for row base + (lane&7) (4x redundant) ----
    const float4 p = params4[base + (lane & 7)];

    const float energy = p.y;
    const float tilt   = p.z * 2.0f - 1.0f;

    // Replicate XLA's separate-op fp32 rounding at the int-trunc boundary:
    const float bandwidth = __fadd_rn(0.05f, __fmul_rn(p.w, 0.95f));
    const float dval      = __fmul_rn(64.0f,
                              __fadd_rn(0.5f, __fmul_rn(0.5f, bandwidth)));
    int delay = (int)dval;
    delay = min(max(delay, 1), 480);

    const float attack_samples =
        fmaxf((0.0005f + p.x * 0.0495f) * 16000.0f, 1.0f);
    const float r    = __expf(-1.0f / attack_samples);
    const float r2t  = r * r;
    const float r4t  = r2t * r2t;
    const float r8t  = r4t * r4t;
    const float r16t = r8t * r8t;
    const float r32  = r16t * r16t;

    // loop-invariant lane predicates for the power decomposition
    const bool l1  = (lane & 1)  != 0;
    const bool l2  = (lane & 2)  != 0;
    const bool l4  = (lane & 4)  != 0;
    const bool l8  = (lane & 8)  != 0;
    const bool l16 = (lane & 16) != 0;

    const float* __restrict__ nrow = noise + (size_t)base * 64 + lane;
    float*       __restrict__ orow = out   + (size_t)base * 64 + lane;

    #pragma unroll
    for (int j = 0; j < BATCH; j++) {
        // broadcast row j's scalars from lane j
        const float rj   = __shfl_sync(0xffffffffu, r,      j);
        const float r32j = __shfl_sync(0xffffffffu, r32,    j);
        const float ej   = __shfl_sync(0xffffffffu, energy, j);
        const float tj   = __shfl_sync(0xffffffffu, tilt,   j);
        const int   dj   = __shfl_sync(0xffffffffu, delay,  j);

        // e = energy * rj^lane via 4 squarings + 5 predicated multiplies
        const float q2  = rj * rj;
        const float q4  = q2 * q2;
        const float q8  = q4 * q4;
        const float q16 = q8 * q8;
        float e = ej;
        if (l1)  e *= rj;
        if (l2)  e *= q2;
        if (l4)  e *= q4;
        if (l8)  e *= q8;
        if (l16) e *= q16;            // e = energy * rj^lane
        const float ee1 = e * r32j;   // energy * rj^(lane+32)

        const float x0 = nrow[j * 64];
        const float x1 = nrow[j * 64 + 32];

        const float b0 = x0 * e;
        const float b1 = x1 * ee1;

        // comb tap: only high half taps; source is the LOW sample of
        // lane (lane+32-delay), which is in [-31, 30] (< 32 always).
        const int   idx = lane + 32 - dj;
        const float src = __shfl_sync(0xffffffffu, b0, idx & 31);
        const float y1  = b1 + ((idx >= 0) ? tj * src : 0.0f);

        // RMS over the 64 samples: warp butterfly reduce
        float ss = fmaf(b0, b0, y1 * y1);
        #pragma unroll
        for (int o = 16; o > 0; o >>= 1)
            ss += __shfl_xor_sync(0xffffffffu, ss, o);

        const float inv = rsqrtf(fmaf(ss, (1.0f / 64.0f), 1e-5f));

        orow[j * 64]      = b0 * inv;
        orow[j * 64 + 32] = y1 * inv;
    }
}

extern "C" void kernel_launch(void* const* d_in, const int* in_sizes, int n_in,
                              void* d_out, int out_size)
{
    const float4* params = (const float4*)d_in[0];  // [32,2000,4]
    const float*  noise  = (const float*)d_in[1];   // [32,2000,64]
    float* out           = (float*)d_out;           // [32, 2000*64]

    (void)in_sizes; (void)n_in; (void)out_size;

    // 8000 warps, one 8-row batch each: 1000 blocks x 256 threads
    const int threads = 256;
    const int blocks  = (NWARPS * 32) / threads;    // 1000
    transient_comb_kernel<<<blocks, threads>>>(params, noise, out);
}